// round 16
// baseline (speedup 1.0000x reference)
#include <cuda_runtime.h>
#include <cuda_bf16.h>
#include <math.h>

#define BATCH 16384
#define MAX_ACTIVE 32
#define FEAT 768
#define HIDDEN 1024
#define TH 128
#define NTILE (HIDDEN / TH)                 // 8
#define NCHUNK 18
#define RPC ((BATCH + NCHUNK - 1) / NCHUNK) // 911 rows per chunk
#define NWARP 32
#define NTHREADS (NWARP * 32)               // 1024

#define TILE_BYTES ((FEAT + 1) * TH * 2)    // 196864
#define SM_OWS TILE_BYTES
#define SM_OWN (SM_OWS + 512)
#define SM_STAGE (SM_OWN + 512)             // 32 warps x 256B staging
#define SMEM_BYTES (SM_STAGE + NWARP * 256) // 206080

__device__ __align__(16) __nv_bfloat16 g_wt[FEAT * HIDDEN]; // wt[f][h]
__device__ float g_part[BATCH * NTILE];                     // [row][tile]

__global__ void dummy_kernel() {} // x2 => 4th launch overall = gather_kernel (ncu slot)

// ---------------- prep: transpose ft_w (HIDDEN,FEAT) fp32 -> g_wt (FEAT,HIDDEN) bf16
__global__ void prep_kernel(const float* __restrict__ ft_w) {
    __shared__ float s[32][33];
    int f0 = blockIdx.x * 32;
    int h0 = blockIdx.y * 32;
    int tx = threadIdx.x, ty = threadIdx.y; // 32 x 8
#pragma unroll
    for (int j = 0; j < 4; j++)
        s[ty + 8 * j][tx] = ft_w[(h0 + ty + 8 * j) * FEAT + f0 + tx];
    __syncthreads();
#pragma unroll
    for (int j = 0; j < 4; j++) {
        int fl = ty + 8 * j;
        g_wt[(f0 + fl) * HIDDEN + (h0 + tx)] = __float2bfloat16(s[tx][fl]);
    }
}

// pairwise bf16x2 add (FMA pipe)
__device__ __forceinline__ unsigned hadd2bf(unsigned a, unsigned b) {
    unsigned r;
    asm("add.rn.bf16x2 %0, %1, %2;" : "=r"(r) : "r"(a), "r"(b));
    return r;
}
// bf16 pair (packed u32) accumulated into f32x2 accumulator
__device__ __forceinline__ void acc_bf2(unsigned w, unsigned long long& a) {
    asm("{\n\t"
        ".reg .b32 lo, hi;\n\t"
        ".reg .b64 v;\n\t"
        "shl.b32 lo, %1, 16;\n\t"
        "and.b32 hi, %1, 0xffff0000;\n\t"
        "mov.b64 v, {lo, hi};\n\t"
        "add.rn.f32x2 %0, %0, v;\n\t"
        "}" : "+l"(a) : "r"(w));
}
__device__ __forceinline__ float2 unpk2(unsigned long long a) {
    float2 r;
    asm("mov.b64 {%0, %1}, %2;" : "=f"(r.x), "=f"(r.y) : "l"(a));
    return r;
}
// pack two f32 into bf16x2 (lo, hi)
__device__ __forceinline__ unsigned pkbf2(float lo, float hi) {
    unsigned r;
    asm("cvt.rn.bf16x2.f32 %0, %2, %1;" : "=r"(r) : "f"(lo), "f"(hi));
    return r;
}
// set-semantics dedup; invalid/dupe -> FEAT (zero row)
__device__ __forceinline__ int dedup(int v, int lane) {
    unsigned m = __match_any_sync(0xffffffffu, v);
    return (v < 0 || (__ffs(m) - 1) != lane) ? FEAT : v;
}

// 4 features (u16 x4 packed in a uint2): two LDS.128 + accumulate
__device__ __forceinline__ void acc4(const unsigned char* tbase, unsigned ua, unsigned ub,
                                     unsigned long long& a0, unsigned long long& a1,
                                     unsigned long long& a2, unsigned long long& a3) {
    unsigned f0 = (ua & 0xffffu) << 8;
    unsigned f1 = (ua >> 16) << 8;
    unsigned f2 = (ub & 0xffffu) << 8;
    unsigned f3 = (ub >> 16) << 8;
    uint4 w0 = *(const uint4*)(tbase + f0);
    uint4 w1 = *(const uint4*)(tbase + f1);
    uint4 w2 = *(const uint4*)(tbase + f2);
    uint4 w3 = *(const uint4*)(tbase + f3);
    acc_bf2(hadd2bf(w0.x, w1.x), a0);
    acc_bf2(hadd2bf(w0.y, w1.y), a1);
    acc_bf2(hadd2bf(w0.z, w1.z), a2);
    acc_bf2(hadd2bf(w0.w, w1.w), a3);
    acc_bf2(hadd2bf(w2.x, w3.x), a0);
    acc_bf2(hadd2bf(w2.y, w3.y), a1);
    acc_bf2(hadd2bf(w2.z, w3.z), a2);
    acc_bf2(hadd2bf(w2.w, w3.w), a3);
}

// clamp accumulators, dot with 8 out_w from smem
__device__ __forceinline__ float dot8s(unsigned long long a0, unsigned long long a1,
                                       unsigned long long a2, unsigned long long a3,
                                       const unsigned char* wp) {
    float4 t0 = *(const float4*)(wp);
    float4 t1 = *(const float4*)(wp + 16);
    float2 v;
    float acc;
    v = unpk2(a0); acc  = __saturatef(v.x) * t0.x + __saturatef(v.y) * t0.y;
    v = unpk2(a1); acc += __saturatef(v.x) * t0.z + __saturatef(v.y) * t0.w;
    v = unpk2(a2); acc += __saturatef(v.x) * t1.x + __saturatef(v.y) * t1.y;
    v = unpk2(a3); acc += __saturatef(v.x) * t1.z + __saturatef(v.y) * t1.w;
    return acc;
}

// ---------------- main gather: 2 rows/warp, interleaved stm/nstm chains
__global__ void __launch_bounds__(NTHREADS, 1)
gather_kernel(const int* __restrict__ stm, const int* __restrict__ nstm,
              const float* __restrict__ ft_b, const float* __restrict__ out_w) {
    extern __shared__ __align__(16) unsigned char smem[];

    const int tileIdx = blockIdx.y;
    const int h0 = tileIdx * TH;

    {
        uint4* dtile = (uint4*)smem;
        const uint4* src = (const uint4*)g_wt;
        const int U4 = TH / 8; // 16 uint4 per row
        for (int i = threadIdx.x; i < FEAT * U4; i += NTHREADS) {
            int f = i >> 4;
            int c = i & 15;
            dtile[i] = src[f * (HIDDEN / 8) + h0 / 8 + c];
        }
        if (threadIdx.x < U4) dtile[FEAT * U4 + threadIdx.x] = make_uint4(0, 0, 0, 0);
        float* sws = (float*)(smem + SM_OWS);
        float* swn = (float*)(smem + SM_OWN);
        if (threadIdx.x >= NTHREADS - TH) {
            int t = threadIdx.x - (NTHREADS - TH);
            sws[t] = out_w[h0 + t];
            swn[t] = out_w[HIDDEN + h0 + t];
        }
    }

    const int lane = threadIdx.x & 31;
    const int warp = threadIdx.x >> 5;
    const int l16 = lane & 15;
    const bool hi_half = lane >= 16;

    // bias for this lane's 8 h, packed bf16x2 (4 regs)
    const int hl = h0 + l16 * 8;
    unsigned fbb0, fbb1, fbb2, fbb3;
    {
        float4 b0 = *(const float4*)(ft_b + hl);
        float4 b1 = *(const float4*)(ft_b + hl + 4);
        fbb0 = pkbf2(b0.x, b0.y); fbb1 = pkbf2(b0.z, b0.w);
        fbb2 = pkbf2(b1.x, b1.y); fbb3 = pkbf2(b1.z, b1.w);
    }
    __syncthreads();

    const int row0 = blockIdx.x * RPC;
    const int row1 = min(row0 + RPC, BATCH);
    const int npairs = (row1 - row0 + 1) >> 1;

    const unsigned char* tbase = smem + l16 * 16;
    unsigned char* stg = smem + SM_STAGE + warp * 256;
    const unsigned char* myS = stg + (hi_half ? 64 : 0);
    const unsigned char* myN = myS + 128;
    const unsigned char* wsp = smem + SM_OWS + l16 * 32;
    const unsigned char* wnp = smem + SM_OWN + l16 * 32;

    // prefetch first pair's raw indices
    int4 cur = make_int4(0, 0, 0, 0);
    if (warp < npairs) {
        const int r0 = row0 + 2 * warp;
        const int r1 = min(r0 + 1, row1 - 1);
        cur.x = stm[r0 * MAX_ACTIVE + lane];
        cur.y = stm[r1 * MAX_ACTIVE + lane];
        cur.z = nstm[r0 * MAX_ACTIVE + lane];
        cur.w = nstm[r1 * MAX_ACTIVE + lane];
    }

    for (int p = warp; p < npairs; p += NWARP) {
        const int r0 = row0 + 2 * p;
        const int r1 = r0 + 1;
        const bool has1 = (r1 < row1);

        // dedup + stage current pair's indices
        int d0s = dedup(cur.x, lane);
        int d1s = dedup(cur.y, lane);
        int d0n = dedup(cur.z, lane);
        int d1n = dedup(cur.w, lane);
        *(unsigned short*)(stg + lane * 2) = (unsigned short)d0s;
        *(unsigned short*)(stg + 64 + lane * 2) = (unsigned short)d1s;
        *(unsigned short*)(stg + 128 + lane * 2) = (unsigned short)d0n;
        *(unsigned short*)(stg + 192 + lane * 2) = (unsigned short)d1n;
        __syncwarp();

        // prefetch NEXT pair's raw indices (overlaps accumulation below)
        const int pn = p + NWARP;
        if (pn < npairs) {
            const int nr0 = row0 + 2 * pn;
            const int nr1 = min(nr0 + 1, row1 - 1);
            cur.x = stm[nr0 * MAX_ACTIVE + lane];
            cur.y = stm[nr1 * MAX_ACTIVE + lane];
            cur.z = nstm[nr0 * MAX_ACTIVE + lane];
            cur.w = nstm[nr1 * MAX_ACTIVE + lane];
        }

        // ---- interleaved stm + nstm accumulation: 8 independent f32x2 chains
        unsigned long long s0 = 0, s1 = 0, s2 = 0, s3 = 0;
        unsigned long long n0 = 0, n1 = 0, n2 = 0, n3 = 0;
        acc_bf2(fbb0, s0); acc_bf2(fbb1, s1); acc_bf2(fbb2, s2); acc_bf2(fbb3, s3);
        acc_bf2(fbb0, n0); acc_bf2(fbb1, n1); acc_bf2(fbb2, n2); acc_bf2(fbb3, n3);
#pragma unroll
        for (int j = 0; j < 4; j++) {
            uint2 ixS = *(const uint2*)(myS + j * 16);      // 4 stm idx
            uint2 ixN = *(const uint2*)(myN + j * 16);      // 4 nstm idx
            uint2 ixS2 = *(const uint2*)(myS + j * 16 + 8); // 4 more stm
            uint2 ixN2 = *(const uint2*)(myN + j * 16 + 8); // 4 more nstm
            acc4(tbase, ixS.x, ixS.y, s0, s1, s2, s3);
            acc4(tbase, ixN.x, ixN.y, n0, n1, n2, n3);
            acc4(tbase, ixS2.x, ixS2.y, s0, s1, s2, s3);
            acc4(tbase, ixN2.x, ixN2.y, n0, n1, n2, n3);
        }
        float acc = dot8s(s0, s1, s2, s3, wsp) + dot8s(n0, n1, n2, n3, wnp);

        // reduce within each 16-lane half (also reconverges warp before next STS)
#pragma unroll
        for (int off = 8; off > 0; off >>= 1)
            acc += __shfl_xor_sync(0xffffffffu, acc, off);

        if (lane == 0) g_part[r0 * NTILE + tileIdx] = acc;
        if (lane == 16 && has1) g_part[r1 * NTILE + tileIdx] = acc;
    }
}

// ---------------- finish: coalesced per-row partial sum + sigmoid
__global__ void finish_kernel(const float* __restrict__ out_b, float* __restrict__ out) {
    int i = blockIdx.x * blockDim.x + threadIdx.x;
    if (i < BATCH) {
        const float4* p = (const float4*)(g_part + i * NTILE);
        float4 x = p[0], y = p[1];
        float z = out_b[0] + x.x + x.y + x.z + x.w + y.x + y.y + y.z + y.w;
        out[i] = 1.0f / (1.0f + __expf(-z));
    }
}

extern "C" void kernel_launch(void* const* d_in, const int* in_sizes, int n_in,
                              void* d_out, int out_size) {
    const int* stm = (const int*)d_in[0];
    const int* nstm = (const int*)d_in[1];
    const float* ft_w = (const float*)d_in[2];
    const float* ft_b = (const float*)d_in[3];
    const float* out_w = (const float*)d_in[4];
    const float* out_b = (const float*)d_in[5];
    float* out = (float*)d_out;

    cudaFuncSetAttribute(gather_kernel, cudaFuncAttributeMaxDynamicSharedMemorySize,
                         SMEM_BYTES);

    dummy_kernel<<<1, 32>>>();
    dummy_kernel<<<1, 32>>>();
    prep_kernel<<<dim3(FEAT / 32, HIDDEN / 32), dim3(32, 8)>>>(ft_w);
    gather_kernel<<<dim3(NCHUNK, NTILE), NTHREADS, SMEM_BYTES>>>(stm, nstm, ft_b, out_w);
    finish_kernel<<<(BATCH + 127) / 128, 128>>>(out_b, out);
}

// round 17
// speedup vs baseline: 1.0726x; 1.0726x over previous
#include <cuda_runtime.h>
#include <cuda_bf16.h>
#include <math.h>

#define BATCH 16384
#define MAX_ACTIVE 32
#define FEAT 768
#define HIDDEN 1024
#define TH 128
#define NTILE (HIDDEN / TH)                 // 8
#define NCHUNK 19                           // 19*8 = 152 CTAs = GB300 SM count
#define RPC ((BATCH + NCHUNK - 1) / NCHUNK) // 863 rows per chunk
#define NWARP 32
#define NTHREADS (NWARP * 32)               // 1024

#define TILE_BYTES ((FEAT + 1) * TH * 2)    // 196864
#define SM_OWS TILE_BYTES
#define SM_OWN (SM_OWS + 512)
#define SM_STAGE (SM_OWN + 512)             // 32 warps x 256B staging
#define SMEM_BYTES (SM_STAGE + NWARP * 256) // 206080

__device__ __align__(16) __nv_bfloat16 g_wt[FEAT * HIDDEN]; // wt[f][h]
__device__ float g_part[BATCH * NTILE];                     // [row][tile]

__global__ void dummy_kernel() {} // x2 => 4th launch overall = gather_kernel (ncu slot)

// ---------------- prep: transpose ft_w (HIDDEN,FEAT) fp32 -> g_wt (FEAT,HIDDEN) bf16
__global__ void prep_kernel(const float* __restrict__ ft_w) {
    __shared__ float s[32][33];
    int f0 = blockIdx.x * 32;
    int h0 = blockIdx.y * 32;
    int tx = threadIdx.x, ty = threadIdx.y; // 32 x 8
#pragma unroll
    for (int j = 0; j < 4; j++)
        s[ty + 8 * j][tx] = ft_w[(h0 + ty + 8 * j) * FEAT + f0 + tx];
    __syncthreads();
#pragma unroll
    for (int j = 0; j < 4; j++) {
        int fl = ty + 8 * j;
        g_wt[(f0 + fl) * HIDDEN + (h0 + tx)] = __float2bfloat16(s[tx][fl]);
    }
}

// pairwise bf16x2 add (FMA pipe)
__device__ __forceinline__ unsigned hadd2bf(unsigned a, unsigned b) {
    unsigned r;
    asm("add.rn.bf16x2 %0, %1, %2;" : "=r"(r) : "r"(a), "r"(b));
    return r;
}
// bf16 pair (packed u32) accumulated into f32x2 accumulator
__device__ __forceinline__ void acc_bf2(unsigned w, unsigned long long& a) {
    asm("{\n\t"
        ".reg .b32 lo, hi;\n\t"
        ".reg .b64 v;\n\t"
        "shl.b32 lo, %1, 16;\n\t"
        "and.b32 hi, %1, 0xffff0000;\n\t"
        "mov.b64 v, {lo, hi};\n\t"
        "add.rn.f32x2 %0, %0, v;\n\t"
        "}" : "+l"(a) : "r"(w));
}
__device__ __forceinline__ float2 unpk2(unsigned long long a) {
    float2 r;
    asm("mov.b64 {%0, %1}, %2;" : "=f"(r.x), "=f"(r.y) : "l"(a));
    return r;
}
// pack two f32 into bf16x2 (lo, hi)
__device__ __forceinline__ unsigned pkbf2(float lo, float hi) {
    unsigned r;
    asm("cvt.rn.bf16x2.f32 %0, %2, %1;" : "=r"(r) : "f"(lo), "f"(hi));
    return r;
}
// set-semantics dedup; invalid/dupe -> FEAT (zero row)
__device__ __forceinline__ int dedup(int v, int lane) {
    unsigned m = __match_any_sync(0xffffffffu, v);
    return (v < 0 || (__ffs(m) - 1) != lane) ? FEAT : v;
}

// process 8 features packed as u16 x8 in a uint4 (byte offsets = f*256)
__device__ __forceinline__ void acc8(const unsigned char* tbase, uint4 ix,
                                     unsigned long long& a0, unsigned long long& a1,
                                     unsigned long long& a2, unsigned long long& a3) {
#pragma unroll
    for (int q = 0; q < 4; q++) {
        unsigned u = (q == 0) ? ix.x : (q == 1) ? ix.y : (q == 2) ? ix.z : ix.w;
        unsigned f0 = (u & 0xffffu) << 8;   // *256
        unsigned f1 = (u >> 16) << 8;
        uint4 w = *(const uint4*)(tbase + f0);
        uint4 w2 = *(const uint4*)(tbase + f1);
        acc_bf2(hadd2bf(w.x, w2.x), a0);
        acc_bf2(hadd2bf(w.y, w2.y), a1);
        acc_bf2(hadd2bf(w.z, w2.z), a2);
        acc_bf2(hadd2bf(w.w, w2.w), a3);
    }
}

// clamp accumulators, dot with 8 out_w from smem (loaded after accs are free)
__device__ __forceinline__ float dot8s(unsigned long long a0, unsigned long long a1,
                                       unsigned long long a2, unsigned long long a3,
                                       const unsigned char* wp) {
    float4 t0 = *(const float4*)(wp);
    float4 t1 = *(const float4*)(wp + 16);
    float2 v;
    float acc;
    v = unpk2(a0); acc  = __saturatef(v.x) * t0.x + __saturatef(v.y) * t0.y;
    v = unpk2(a1); acc += __saturatef(v.x) * t0.z + __saturatef(v.y) * t0.w;
    v = unpk2(a2); acc += __saturatef(v.x) * t1.x + __saturatef(v.y) * t1.y;
    v = unpk2(a3); acc += __saturatef(v.x) * t1.z + __saturatef(v.y) * t1.w;
    return acc;
}

// ---------------- main gather: 2 rows/warp, pipelined index prefetch
__global__ void __launch_bounds__(NTHREADS, 1)
gather_kernel(const int* __restrict__ stm, const int* __restrict__ nstm,
              const float* __restrict__ ft_b, const float* __restrict__ out_w) {
    extern __shared__ __align__(16) unsigned char smem[];

    const int tileIdx = blockIdx.y;
    const int h0 = tileIdx * TH;

    {
        uint4* dtile = (uint4*)smem;
        const uint4* src = (const uint4*)g_wt;
        const int U4 = TH / 8; // 16 uint4 per row
        for (int i = threadIdx.x; i < FEAT * U4; i += NTHREADS) {
            int f = i >> 4;
            int c = i & 15;
            dtile[i] = src[f * (HIDDEN / 8) + h0 / 8 + c];
        }
        if (threadIdx.x < U4) dtile[FEAT * U4 + threadIdx.x] = make_uint4(0, 0, 0, 0);
        float* sws = (float*)(smem + SM_OWS);
        float* swn = (float*)(smem + SM_OWN);
        if (threadIdx.x >= NTHREADS - TH) {
            int t = threadIdx.x - (NTHREADS - TH);
            sws[t] = out_w[h0 + t];
            swn[t] = out_w[HIDDEN + h0 + t];
        }
    }

    const int lane = threadIdx.x & 31;
    const int warp = threadIdx.x >> 5;
    const int l16 = lane & 15;
    const bool hi_half = lane >= 16;

    // bias for this lane's 8 h, packed bf16x2 (4 regs)
    const int hl = h0 + l16 * 8;
    unsigned fbb0, fbb1, fbb2, fbb3;
    {
        float4 b0 = *(const float4*)(ft_b + hl);
        float4 b1 = *(const float4*)(ft_b + hl + 4);
        fbb0 = pkbf2(b0.x, b0.y); fbb1 = pkbf2(b0.z, b0.w);
        fbb2 = pkbf2(b1.x, b1.y); fbb3 = pkbf2(b1.z, b1.w);
    }
    __syncthreads();

    const int row0 = blockIdx.x * RPC;
    const int row1 = min(row0 + RPC, BATCH);
    const int npairs = (row1 - row0 + 1) >> 1;

    const unsigned char* tbase = smem + l16 * 16;
    unsigned char* stg = smem + SM_STAGE + warp * 256;
    const unsigned char* myS = stg + (hi_half ? 64 : 0);
    const unsigned char* myN = myS + 128;
    const unsigned char* wsp = smem + SM_OWS + l16 * 32;
    const unsigned char* wnp = smem + SM_OWN + l16 * 32;

    // prefetch first pair's raw indices
    int4 cur = make_int4(0, 0, 0, 0);
    if (warp < npairs) {
        const int r0 = row0 + 2 * warp;
        const int r1 = min(r0 + 1, row1 - 1);
        cur.x = stm[r0 * MAX_ACTIVE + lane];
        cur.y = stm[r1 * MAX_ACTIVE + lane];
        cur.z = nstm[r0 * MAX_ACTIVE + lane];
        cur.w = nstm[r1 * MAX_ACTIVE + lane];
    }

    for (int p = warp; p < npairs; p += NWARP) {
        const int r0 = row0 + 2 * p;
        const int r1 = r0 + 1;
        const bool has1 = (r1 < row1);

        // dedup + stage current pair's indices
        int d0s = dedup(cur.x, lane);
        int d1s = dedup(cur.y, lane);
        int d0n = dedup(cur.z, lane);
        int d1n = dedup(cur.w, lane);
        *(unsigned short*)(stg + lane * 2) = (unsigned short)d0s;
        *(unsigned short*)(stg + 64 + lane * 2) = (unsigned short)d1s;
        *(unsigned short*)(stg + 128 + lane * 2) = (unsigned short)d0n;
        *(unsigned short*)(stg + 192 + lane * 2) = (unsigned short)d1n;
        __syncwarp();

        // prefetch NEXT pair's raw indices (overlaps accumulation below)
        const int pn = p + NWARP;
        if (pn < npairs) {
            const int nr0 = row0 + 2 * pn;
            const int nr1 = min(nr0 + 1, row1 - 1);
            cur.x = stm[nr0 * MAX_ACTIVE + lane];
            cur.y = stm[nr1 * MAX_ACTIVE + lane];
            cur.z = nstm[nr0 * MAX_ACTIVE + lane];
            cur.w = nstm[nr1 * MAX_ACTIVE + lane];
        }

        // ---- stm phase: accumulators init from bf16x2 bias regs
        unsigned long long a0 = 0, a1 = 0, a2 = 0, a3 = 0;
        acc_bf2(fbb0, a0); acc_bf2(fbb1, a1);
        acc_bf2(fbb2, a2); acc_bf2(fbb3, a3);
#pragma unroll
        for (int j = 0; j < 4; j++) {
            uint4 ix = *(const uint4*)(myS + j * 16); // 8 idx, broadcast load
            acc8(tbase, ix, a0, a1, a2, a3);
        }
        float acc = dot8s(a0, a1, a2, a3, wsp);

        // ---- nstm phase
        a0 = 0; a1 = 0; a2 = 0; a3 = 0;
        acc_bf2(fbb0, a0); acc_bf2(fbb1, a1);
        acc_bf2(fbb2, a2); acc_bf2(fbb3, a3);
#pragma unroll
        for (int j = 0; j < 4; j++) {
            uint4 ix = *(const uint4*)(myN + j * 16);
            acc8(tbase, ix, a0, a1, a2, a3);
        }
        acc += dot8s(a0, a1, a2, a3, wnp);

        // reduce within each 16-lane half (also reconverges warp before next STS)
#pragma unroll
        for (int off = 8; off > 0; off >>= 1)
            acc += __shfl_xor_sync(0xffffffffu, acc, off);

        if (lane == 0) g_part[r0 * NTILE + tileIdx] = acc;
        if (lane == 16 && has1) g_part[r1 * NTILE + tileIdx] = acc;
    }
}

// ---------------- finish: coalesced per-row partial sum + sigmoid
__global__ void finish_kernel(const float* __restrict__ out_b, float* __restrict__ out) {
    int i = blockIdx.x * blockDim.x + threadIdx.x;
    if (i < BATCH) {
        const float4* p = (const float4*)(g_part + i * NTILE);
        float4 x = p[0], y = p[1];
        float z = out_b[0] + x.x + x.y + x.z + x.w + y.x + y.y + y.z + y.w;
        out[i] = 1.0f / (1.0f + __expf(-z));
    }
}

extern "C" void kernel_launch(void* const* d_in, const int* in_sizes, int n_in,
                              void* d_out, int out_size) {
    const int* stm = (const int*)d_in[0];
    const int* nstm = (const int*)d_in[1];
    const float* ft_w = (const float*)d_in[2];
    const float* ft_b = (const float*)d_in[3];
    const float* out_w = (const float*)d_in[4];
    const float* out_b = (const float*)d_in[5];
    float* out = (float*)d_out;

    cudaFuncSetAttribute(gather_kernel, cudaFuncAttributeMaxDynamicSharedMemorySize,
                         SMEM_BYTES);

    dummy_kernel<<<1, 32>>>();
    dummy_kernel<<<1, 32>>>();
    prep_kernel<<<dim3(FEAT / 32, HIDDEN / 32), dim3(32, 8)>>>(ft_w);
    gather_kernel<<<dim3(NCHUNK, NTILE), NTHREADS, SMEM_BYTES>>>(stm, nstm, ft_b, out_w);
    finish_kernel<<<(BATCH + 127) / 128, 128>>>(out_b, out);
}